// round 8
// baseline (speedup 1.0000x reference)
#include <cuda_runtime.h>
#include <math.h>
#include <stdint.h>

#define NT     1024
#define NWARP  32
#define BB     16
#define TT     32
#define INDIM  256
#define HDIM   512
#define RHEADS 4
#define WDIM   64
#define MDIM   512
#define DELTAF 1e-6f

typedef unsigned long long ull;

// Global scratch (static, no allocation):
__device__ float g_link[(size_t)BB * MDIM * MDIM];            // 16 MB link
__device__ float g_pre[(size_t)BB * 2048 * TT];               // 4 MB x@W_ih^T pre

// ---- packed f32x2 helpers ----
static __device__ __forceinline__ ull pk2(float a, float b) {
    ull r; asm("mov.b64 %0,{%1,%2};" : "=l"(r) : "f"(a), "f"(b)); return r;
}
static __device__ __forceinline__ float2 upk2(ull v) {
    float2 f; asm("mov.b64 {%0,%1},%2;" : "=f"(f.x), "=f"(f.y) : "l"(v)); return f;
}
static __device__ __forceinline__ ull add2(ull a, ull b) {
    ull d; asm("add.rn.f32x2 %0,%1,%2;" : "=l"(d) : "l"(a), "l"(b)); return d;
}
static __device__ __forceinline__ ull mul2(ull a, ull b) {
    ull d; asm("mul.rn.f32x2 %0,%1,%2;" : "=l"(d) : "l"(a), "l"(b)); return d;
}
static __device__ __forceinline__ ull fma2(ull a, ull b, ull c) {
    ull d; asm("fma.rn.f32x2 %0,%1,%2,%3;" : "=l"(d) : "l"(a), "l"(b), "l"(c)); return d;
}

static __device__ __forceinline__ float warp_sum(float v) {
#pragma unroll
    for (int o = 16; o; o >>= 1) v += __shfl_down_sync(0xffffffffu, v, o);
    return v;
}
static __device__ __forceinline__ float sigm(float x)  { return 1.0f / (1.0f + expf(-x)); }
static __device__ __forceinline__ float splus(float x) { return fmaxf(x, 0.0f) + log1pf(expf(-fabsf(x))); }

static __device__ __forceinline__ float block_sum(float v, float* red) {
    int warp = threadIdx.x >> 5, lane = threadIdx.x & 31;
    v = warp_sum(v);
    if (!lane) red[warp] = v;
    __syncthreads();
    if (warp == 0) { float q = red[lane]; q = warp_sum(q); if (!lane) red[0] = q; }
    __syncthreads();
    float r = red[0];
    __syncthreads();
    return r;
}

// Single-warp softmax over arr[0..511]; only the executing warp participates.
static __device__ __forceinline__ void warp_softmax512(float* arr) {
    int lane = threadIdx.x & 31;
    float v[16];
    float mx = -3.402823466e38f;
#pragma unroll
    for (int k = 0; k < 16; k++) { v[k] = arr[lane + 32 * k]; mx = fmaxf(mx, v[k]); }
#pragma unroll
    for (int o = 16; o; o >>= 1) mx = fmaxf(mx, __shfl_xor_sync(0xffffffffu, mx, o));
    float s = 0.0f;
#pragma unroll
    for (int k = 0; k < 16; k++) { v[k] = expf(v[k] - mx); s += v[k]; }
#pragma unroll
    for (int o = 16; o; o >>= 1) s += __shfl_xor_sync(0xffffffffu, s, o);
    float inv = 1.0f / s;
#pragma unroll
    for (int k = 0; k < 16; k++) arr[lane + 32 * k] = v[k] * inv;
}

#define BARA() asm volatile("bar.sync 1, 512;" ::: "memory")   // warps 0-15
#define BARB() asm volatile("bar.sync 2, 512;" ::: "memory")   // warps 16-31
#define BARC() asm volatile("bar.sync 3, 256;" ::: "memory")   // warps 24-31

extern __shared__ float S[];

__global__ __launch_bounds__(NT, 1)
void dnc_kernel(const float* __restrict__ x,
                const float* __restrict__ W_ih, const float* __restrict__ b_ih,
                const float* __restrict__ W_hh, const float* __restrict__ b_hh,
                const float* __restrict__ W_out, const float* __restrict__ b_out,
                const float* __restrict__ W_int, const float* __restrict__ b_int,
                const float* __restrict__ W_mem, const float* __restrict__ b_mem,
                float* __restrict__ y_out)
{
    const int b    = blockIdx.x;
    const int tid  = threadIdx.x;
    const int warp = tid >> 5;
    const int lane = tid & 31;

    // ---- shared memory layout ----
    float* mem   = S;              // 32768  mem[512][64]
    float* h     = mem + 32768;    // 512
    float* c     = h + 512;        // 512
    float* inp   = c + 512;        // 512 : [unused(256), last_read(256)]
    float* gates = inp + 512;      // 2048 (alias: skey u64[512]; nww at +1024)
    float* outv  = gates + 2048;   // 512
    float* xi    = outv + 512;     // 480
    float* usage = xi + 480;       // 512
    float* wcw   = usage + 512;    // 512
    float* alloc = wcw + 512;      // 512
    float* wwv   = alloc + 512;    // 512
    float* prec  = wwv + 512;      // 512
    float* rw    = prec + 512;     // 2048 : read_w[4][512]
    float* fwd   = rw + 2048;      // 2048 (alias at init: xall staging, spans 8576 floats
                                   //       through ers — all dead at init, rewritten per step)
    float* bwd   = fwd + 2048;     // 2048
    float* rwp01 = bwd + 2048;     // 1024 : float2[512] (rw0,rw1)
    float* rwp23 = rwp01 + 1024;   // 1024 : float2[512] (rw2,rw3)
    float* cw    = rwp23 + 1024;   // 2048
    float* rk    = cw + 2048;      // 256
    float* wkey  = rk + 256;       // 64
    float* ers   = wkey + 64;      // 64
    float* wv    = ers + 64;       // 64
    float* sc    = wv + 64;        // 32
    float* red   = sc + 32;        // 32
    // total 50656 floats = 202624 bytes
    ull*   skey = (ull*)gates;
    float* nww  = gates + 1024;

    float* Lb   = g_link + (size_t)b * MDIM * MDIM;
    float* preb = g_pre + (size_t)b * 2048 * TT;

    // ---- init state ----
    for (int i = tid; i < MDIM * WDIM; i += NT) mem[i] = 0.0f;
    for (int i = tid; i < 512; i += NT) { h[i] = 0.f; c[i] = 0.f; usage[i] = 0.f; prec[i] = 0.f; wwv[i] = 0.f; }
    for (int i = tid; i < 2048; i += NT) rw[i] = 0.0f;
    if (tid < 256) inp[256 + tid] = 0.0f;
    {
        float4* L4 = (float4*)Lb;
        for (int i = tid; i < MDIM * MDIM / 4; i += NT) L4[i] = make_float4(0.f, 0.f, 0.f, 0.f);
    }
    // stage all x_t into smem scratch (fwd.. region; dead at init). Row stride
    // 268 floats (16B aligned).
    {
        float* xall = fwd;
        for (int i = tid; i < TT * INDIM; i += NT) {
            int tt = i >> 8, e = i & 255;
            xall[tt * 268 + e] = x[((size_t)b * TT + tt) * INDIM + e];
        }
    }
    __syncthreads();
    // precompute g_pre[b][o][t] = W_ih[o,0:256] . x_t   (lane = t)
    {
        const float* xall = fwd;
        const ulonglong2* xs = (const ulonglong2*)(xall + lane * 268);
        for (int o = warp; o < 2048; o += NWARP) {
            const float4* wrow = (const float4*)(W_ih + (size_t)o * 512);
            ull acc = 0;
#pragma unroll 8
            for (int k = 0; k < 64; k++) {
                float4 w = wrow[k];          // uniform across lanes (broadcast)
                ulonglong2 xv = xs[k];
                acc = fma2(xv.x, pk2(w.x, w.y), acc);
                acc = fma2(xv.y, pk2(w.z, w.w), acc);
            }
            float2 f = upk2(acc);
            preb[(size_t)o * TT + lane] = f.x + f.y;
        }
    }
    __syncthreads();

    for (int t = 0; t < TT; t++) {
        // ---- 1. gates GEMV: pre[o][t] + W_ih[o,256:512].last_read + W_hh[o].h ----
        {
            const ulonglong2* vr = (const ulonglong2*)(inp + 256);
            const ulonglong2* vh = (const ulonglong2*)h;
            for (int o = warp; o < 4 * HDIM; o += NWARP) {
                float pre = preb[(size_t)o * TT + t];   // broadcast load, issued early
                const ulonglong2* wr = (const ulonglong2*)(W_ih + (size_t)o * 512 + 256);
                const ulonglong2* wh = (const ulonglong2*)(W_hh + (size_t)o * 512);
                ull acc = 0;
#pragma unroll
                for (int kk = 0; kk < 2; kk++) {
                    int k = lane + (kk << 5);
                    ulonglong2 a = wr[k], p = vr[k];
                    acc = fma2(a.x, p.x, acc);
                    acc = fma2(a.y, p.y, acc);
                }
#pragma unroll
                for (int kk = 0; kk < 4; kk++) {
                    int k = lane + (kk << 5);
                    ulonglong2 a = wh[k], p = vh[k];
                    acc = fma2(a.x, p.x, acc);
                    acc = fma2(a.y, p.y, acc);
                }
                float2 f = upk2(acc);
                float s = warp_sum(f.x + f.y);
                if (!lane) gates[o] = s + pre + b_ih[o] + b_hh[o];
            }
        }
        __syncthreads();

        // ---- 2. LSTM cell ----
        if (tid < HDIM) {
            float gi = sigm(gates[tid]);
            float gf = sigm(gates[HDIM + tid]);
            float gg = tanhf(gates[2 * HDIM + tid]);
            float go = sigm(gates[3 * HDIM + tid]);
            float cn = gf * c[tid] + gi * gg;
            c[tid] = cn;
            h[tid] = go * tanhf(cn);
        }
        __syncthreads();

        // ---- 3. out/xi GEMV ----
        {
            const ulonglong2* vh = (const ulonglong2*)h;
            for (int o = warp; o < 983; o += NWARP) {
                const float* wr = (o < 512) ? (W_out + (size_t)o * 512)
                                            : (W_int + (size_t)(o - 512) * 512);
                const ulonglong2* w2 = (const ulonglong2*)wr;
                ull acc = 0;
#pragma unroll
                for (int kk = 0; kk < 4; kk++) {
                    int k = lane + (kk << 5);
                    ulonglong2 a = w2[k], p = vh[k];
                    acc = fma2(a.x, p.x, acc);
                    acc = fma2(a.y, p.y, acc);
                }
                float2 f = upk2(acc);
                float s = warp_sum(f.x + f.y);
                if (!lane) {
                    if (o < 512) outv[o] = s + b_out[o];
                    else         xi[o - 512] = s + b_int[o - 512];
                }
            }
        }
        __syncthreads();

        // ---- 4. parse interface ----
        if (tid < 256)       rk[tid]         = tanhf(xi[tid]);
        else if (tid < 320)  wkey[tid - 256] = tanhf(xi[260 + (tid - 256)]);
        else if (tid < 384)  ers[tid - 320]  = sigm(xi[325 + (tid - 320)]);
        else if (tid < 448)  wv[tid - 384]   = tanhf(xi[389 + (tid - 384)]);
        else if (tid < 452)  sc[5 + (tid - 448)]  = splus(xi[256 + (tid - 448)]);
        else if (tid == 452) sc[9]  = splus(xi[324]);
        else if (tid < 457)  sc[10 + (tid - 453)] = sigm(xi[453 + (tid - 453)]);
        else if (tid == 457) sc[14] = sigm(xi[457]);
        else if (tid == 458) sc[15] = sigm(xi[458]);
        else if (tid < 463) {
            int r = tid - 459;
            float a = xi[459 + 3 * r], bm = xi[460 + 3 * r], cm = xi[461 + 3 * r];
            float mx = fmaxf(a, fmaxf(bm, cm));
            float ea = expf(a - mx), eb = expf(bm - mx), ec = expf(cm - mx);
            float s = ea + eb + ec;
            sc[16 + 3 * r] = ea / s; sc[17 + 3 * r] = eb / s; sc[18 + 3 * r] = ec / s;
        }
        __syncthreads();

        // ---- 5. key norms + usage update ----
        if (warp < 5) {
            const float* kp = (warp == 0) ? wkey : (rk + (warp - 1) * 64);
            float a = kp[lane], bq = kp[lane + 32];
            float ss = warp_sum(a * a + bq * bq);
            if (!lane) sc[warp] = 1.0f / (sqrtf(ss) + DELTAF);
        }
        if (tid < MDIM) {
            float u = usage[tid];
            u = u + (1.0f - u) * wwv[tid];          // old write_w
            float psi = 1.0f;
#pragma unroll
            for (int r = 0; r < RHEADS; r++) psi *= (1.0f - sc[10 + r] * rw[r * MDIM + tid]);
            usage[tid] = u * psi;
        }
        __syncthreads();

        // ==== SPLIT 1: [warps 0-15] wcw dots+softmax  ||  [16-31] sort+alloc ====
        if (tid < 512) {
            float ikn = sc[0], wstr = sc[9];
            for (int m = warp; m < MDIM; m += 16) {
                float a = mem[m * 64 + lane], bq = mem[m * 64 + lane + 32];
                float ss = a * a + bq * bq;
                float dk = a * wkey[lane] + bq * wkey[lane + 32];
#pragma unroll
                for (int o = 16; o; o >>= 1) {
                    ss += __shfl_down_sync(0xffffffffu, ss, o);
                    dk += __shfl_down_sync(0xffffffffu, dk, o);
                }
                if (!lane) {
                    float im = 1.0f / (sqrtf(ss) + DELTAF);
                    wcw[m] = dk * im * ikn * wstr;
                }
            }
            BARA();
            if (warp == 0) warp_softmax512(wcw);
        } else {
            // stable bitonic over (u, idx) in registers; shfl for j<32
            int p = tid - 512;
            int lane2 = p & 31;
            float u0 = DELTAF + (1.0f - DELTAF) * usage[p];
            ull key = ((ull)__float_as_uint(u0) << 32) | (unsigned)p;
            for (int k = 2; k <= MDIM; k <<= 1) {
                for (int j = k >> 1; j; j >>= 1) {
                    bool up    = ((p & k) == 0);
                    bool lower = ((p & j) == 0);
                    ull v;
                    if (j < 32) {
                        v = __shfl_xor_sync(0xffffffffu, key, j);
                    } else {
                        skey[p] = key;
                        BARB();
                        v = skey[p ^ j];
                        BARB();
                    }
                    bool keepmin = (lower == up);
                    bool take = keepmin ? (v < key) : (v > key);
                    key = take ? v : key;
                }
            }
            // exclusive cumprod of sorted u via warp-shuffle scan
            float su = __uint_as_float((unsigned)(key >> 32));
            float* us = (float*)skey;       // safe: sort's smem phase fully drained
            us[p] = su;
            BARB();
            float v = (p == 0) ? 1.0f : us[p - 1];
#pragma unroll
            for (int o = 1; o < 32; o <<= 1) {
                float tpr = __shfl_up_sync(0xffffffffu, v, o);
                if (lane2 >= o) v *= tpr;
            }
            int wg = p >> 5;
            if (lane2 == 31) red[16 + wg] = v;
            BARB();
            float pre = 1.0f;
            for (int w = 0; w < wg; w++) pre *= red[16 + w];
            unsigned idx = (unsigned)(key & 0xffffffffu);
            alloc[idx] = (1.0f - su) * (pre * v);
        }
        __syncthreads();

        // ---- 6. new write weights (+negated) ----
        if (tid < MDIM) {
            float ag = sc[14], wg = sc[15];
            float w_ = wg * (ag * alloc[tid] + (1.0f - ag) * wcw[tid]);
            wwv[tid] = w_;
            nww[tid] = -w_;
        }
        float sumww = block_sum((tid < MDIM) ? wwv[tid] : 0.0f, red);

        // ==== SPLIT 2: [warps 0-23] link A  ||  [24-31] mem update + cw dots ====
        if (tid < 768) {
            // link pass A: L update + fwd (OLD prec, OLD rw); diagonal post-fix
            const ulonglong2* nw2 = (const ulonglong2*)nww;
            const ulonglong2* pr2 = (const ulonglong2*)prec;
            const ulonglong2* r0b = (const ulonglong2*)(rw);
            const ulonglong2* r1b = (const ulonglong2*)(rw + MDIM);
            const ulonglong2* r2b = (const ulonglong2*)(rw + 2 * MDIM);
            const ulonglong2* r3b = (const ulonglong2*)(rw + 3 * MDIM);
            for (int i = warp; i < MDIM; i += 24) {
                float wwi = wwv[i];
                ull wwi2 = pk2(wwi, wwi);
                ull omw2 = pk2(1.0f - wwi, 1.0f - wwi);
                ull f0 = 0, f1 = 0, f2 = 0, f3 = 0;
                ulonglong2* row = (ulonglong2*)(Lb + (size_t)i * MDIM);
#pragma unroll
                for (int kk = 0; kk < 4; kk++) {
                    int k = lane + (kk << 5);
                    ulonglong2 l  = row[k];
                    ulonglong2 nj = nw2[k], pj = pr2[k];
                    ull c0 = add2(omw2, nj.x);
                    ull c1 = add2(omw2, nj.y);
                    ull n0 = fma2(wwi2, pj.x, mul2(c0, l.x));
                    ull n1 = fma2(wwi2, pj.y, mul2(c1, l.y));
                    ulonglong2 nout; nout.x = n0; nout.y = n1;
                    row[k] = nout;
                    ulonglong2 r0 = r0b[k]; f0 = fma2(n0, r0.x, f0); f0 = fma2(n1, r0.y, f0);
                    ulonglong2 r1 = r1b[k]; f1 = fma2(n0, r1.x, f1); f1 = fma2(n1, r1.y, f1);
                    ulonglong2 r2 = r2b[k]; f2 = fma2(n0, r2.x, f2); f2 = fma2(n1, r2.y, f2);
                    ulonglong2 r3 = r3b[k]; f3 = fma2(n0, r3.x, f3); f3 = fma2(n1, r3.y, f3);
                }
                float2 a0 = upk2(f0), a1 = upk2(f1), a2 = upk2(f2), a3 = upk2(f3);
                float s0 = warp_sum(a0.x + a0.y);
                float s1 = warp_sum(a1.x + a1.y);
                float s2 = warp_sum(a2.x + a2.y);
                float s3 = warp_sum(a3.x + a3.y);
                if (!lane) {
                    float corr = wwi * prec[i];   // OLD prec
                    fwd[i]            = s0 - corr * rw[i];
                    fwd[MDIM + i]     = s1 - corr * rw[MDIM + i];
                    fwd[2 * MDIM + i] = s2 - corr * rw[2 * MDIM + i];
                    fwd[3 * MDIM + i] = s3 - corr * rw[3 * MDIM + i];
                    Lb[(size_t)i * MDIM + i] = 0.0f;
                }
            }
        } else {
            int p3 = tid - 768;   // 0..255
            // zero bwd + stage OLD-rw head pairs for link B
            for (int q = p3; q < 2048; q += 256) bwd[q] = 0.0f;
            for (int q = p3; q < 512; q += 256) {
                ((float2*)rwp01)[q] = make_float2(rw[q], rw[MDIM + q]);
                ((float2*)rwp23)[q] = make_float2(rw[2 * MDIM + q], rw[3 * MDIM + q]);
            }
            // memory update
            for (int i = p3; i < MDIM * WDIM; i += 256) {
                int m = i >> 6, w_ = i & 63;
                float wwm = wwv[m];
                mem[i] = mem[i] * (1.0f - wwm * ers[w_]) + wwm * wv[w_];
            }
            BARC();
            // read content dots (NEW mem)
            for (int m = warp - 24; m < MDIM; m += 8) {
                float a = mem[m * 64 + lane], bq = mem[m * 64 + lane + 32];
                float ss = a * a + bq * bq;
                float d0 = a * rk[lane]       + bq * rk[lane + 32];
                float d1 = a * rk[64 + lane]  + bq * rk[96 + lane];
                float d2 = a * rk[128 + lane] + bq * rk[160 + lane];
                float d3 = a * rk[192 + lane] + bq * rk[224 + lane];
#pragma unroll
                for (int o = 16; o; o >>= 1) {
                    ss += __shfl_down_sync(0xffffffffu, ss, o);
                    d0 += __shfl_down_sync(0xffffffffu, d0, o);
                    d1 += __shfl_down_sync(0xffffffffu, d1, o);
                    d2 += __shfl_down_sync(0xffffffffu, d2, o);
                    d3 += __shfl_down_sync(0xffffffffu, d3, o);
                }
                if (!lane) {
                    float im = 1.0f / (sqrtf(ss) + DELTAF);
                    cw[m]            = d0 * im * sc[1] * sc[5];
                    cw[MDIM + m]     = d1 * im * sc[2] * sc[6];
                    cw[2 * MDIM + m] = d2 * im * sc[3] * sc[7];
                    cw[3 * MDIM + m] = d3 * im * sc[4] * sc[8];
                }
            }
        }
        __syncthreads();

        // ---- 7. precedence update (link A consumed OLD prec) ----
        if (tid < MDIM) prec[tid] = (1.0f - sumww) * prec[tid] + wwv[tid];

        // ---- 8. link pass B: bwd[h][j] = sum_i rw_h[i] * L_new[i][j] ----
        {
            int ig = warp >> 2, jb = warp & 3;
            const float* Lbase = Lb + (size_t)(ig * 64) * MDIM + jb * 128 + lane * 4;
            const ull* rp01 = (const ull*)rwp01 + ig * 64;
            const ull* rp23 = (const ull*)rwp23 + ig * 64;
            ull b01[4] = {0, 0, 0, 0}, b23[4] = {0, 0, 0, 0};
#pragma unroll 4
            for (int ii = 0; ii < 64; ii++) {
                float4 l = *(const float4*)(Lbase + (size_t)ii * MDIM);
                ull r01 = rp01[ii], r23 = rp23[ii];
                ull l0 = pk2(l.x, l.x), l1 = pk2(l.y, l.y);
                ull l2 = pk2(l.z, l.z), l3 = pk2(l.w, l.w);
                b01[0] = fma2(l0, r01, b01[0]); b01[1] = fma2(l1, r01, b01[1]);
                b01[2] = fma2(l2, r01, b01[2]); b01[3] = fma2(l3, r01, b01[3]);
                b23[0] = fma2(l0, r23, b23[0]); b23[1] = fma2(l1, r23, b23[1]);
                b23[2] = fma2(l2, r23, b23[2]); b23[3] = fma2(l3, r23, b23[3]);
            }
            int jbase = jb * 128 + lane * 4;
#pragma unroll
            for (int e = 0; e < 4; e++) {
                float2 v01 = upk2(b01[e]), v23 = upk2(b23[e]);
                atomicAdd(&bwd[jbase + e],            v01.x);
                atomicAdd(&bwd[MDIM + jbase + e],     v01.y);
                atomicAdd(&bwd[2 * MDIM + jbase + e], v23.x);
                atomicAdd(&bwd[3 * MDIM + jbase + e], v23.y);
            }
        }
        __syncthreads();

        // ---- 9. softmax read-content weights ----
        if (warp < 4) warp_softmax512(cw + warp * MDIM);
        __syncthreads();

        // ---- 10. new read weights ----
        for (int q = tid; q < RHEADS * MDIM; q += NT) {
            int r = q >> 9;
            rw[q] = sc[16 + 3 * r] * bwd[q] + sc[17 + 3 * r] * fwd[q] + sc[18 + 3 * r] * cw[q];
        }
        __syncthreads();

        // ---- 11. read vectors -> last_read ----
        {
            int pair = tid >> 2, q4 = tid & 3;
            int r = pair >> 6, w_ = pair & 63;
            const float* rwr = rw + r * MDIM;
            float acc = 0.0f;
            int m0 = q4 << 7;
#pragma unroll 8
            for (int mm = m0; mm < m0 + 128; mm++) acc += rwr[mm] * mem[mm * 64 + w_];
#pragma unroll
            for (int o = 2; o; o >>= 1) acc += __shfl_down_sync(0xffffffffu, acc, o, 4);
            if (q4 == 0) inp[256 + pair] = acc;
        }
        __syncthreads();

        // ---- 12. output GEMV ----
        {
            float* yrow = y_out + ((size_t)b * TT + t) * INDIM;
            const ulonglong2* v1 = (const ulonglong2*)outv;
            const ulonglong2* v2 = (const ulonglong2*)(inp + 256);
            for (int o = warp; o < INDIM; o += NWARP) {
                const ulonglong2* w2 = (const ulonglong2*)(W_mem + (size_t)o * 768);
                ull acc = 0;
#pragma unroll
                for (int kk = 0; kk < 6; kk++) {
                    int k = lane + (kk << 5);
                    ulonglong2 a = w2[k];
                    ulonglong2 p = (k < 128) ? v1[k] : v2[k - 128];
                    acc = fma2(a.x, p.x, acc);
                    acc = fma2(a.y, p.y, acc);
                }
                float2 f = upk2(acc);
                float s = warp_sum(f.x + f.y);
                if (!lane) yrow[o] = s + b_mem[o];
            }
        }
        __syncthreads();
    }
}

extern "C" void kernel_launch(void* const* d_in, const int* in_sizes, int n_in,
                              void* d_out, int out_size) {
    (void)in_sizes; (void)n_in; (void)out_size;
    const int SMEM_BYTES = 50656 * 4;  // 202624
    cudaFuncSetAttribute(dnc_kernel, cudaFuncAttributeMaxDynamicSharedMemorySize, SMEM_BYTES);
    dnc_kernel<<<BB, NT, SMEM_BYTES>>>(
        (const float*)d_in[0],
        (const float*)d_in[1], (const float*)d_in[2],
        (const float*)d_in[3], (const float*)d_in[4],
        (const float*)d_in[5], (const float*)d_in[6],
        (const float*)d_in[7], (const float*)d_in[8],
        (const float*)d_in[9], (const float*)d_in[10],
        (float*)d_out);
}

// round 11
// speedup vs baseline: 1.0959x; 1.0959x over previous
#include <cuda_runtime.h>
#include <math.h>
#include <stdint.h>

#define NT     1024
#define NWARP  32
#define BB     16
#define TT     32
#define INDIM  256
#define HDIM   512
#define RHEADS 4
#define WDIM   64
#define MDIM   512
#define DELTAF 1e-6f

typedef unsigned long long ull;

// Global scratch (static, no allocation):
__device__ float g_link[(size_t)BB * MDIM * MDIM];            // 16 MB link
__device__ float g_pre[(size_t)BB * 2048 * TT];               // 4 MB x@W_ih^T pre

// ---- packed f32x2 helpers ----
static __device__ __forceinline__ ull pk2(float a, float b) {
    ull r; asm("mov.b64 %0,{%1,%2};" : "=l"(r) : "f"(a), "f"(b)); return r;
}
static __device__ __forceinline__ float2 upk2(ull v) {
    float2 f; asm("mov.b64 {%0,%1},%2;" : "=f"(f.x), "=f"(f.y) : "l"(v)); return f;
}
static __device__ __forceinline__ ull add2(ull a, ull b) {
    ull d; asm("add.rn.f32x2 %0,%1,%2;" : "=l"(d) : "l"(a), "l"(b)); return d;
}
static __device__ __forceinline__ ull mul2(ull a, ull b) {
    ull d; asm("mul.rn.f32x2 %0,%1,%2;" : "=l"(d) : "l"(a), "l"(b)); return d;
}
static __device__ __forceinline__ ull fma2(ull a, ull b, ull c) {
    ull d; asm("fma.rn.f32x2 %0,%1,%2,%3;" : "=l"(d) : "l"(a), "l"(b), "l"(c)); return d;
}

static __device__ __forceinline__ float warp_sum(float v) {
#pragma unroll
    for (int o = 16; o; o >>= 1) v += __shfl_down_sync(0xffffffffu, v, o);
    return v;
}
static __device__ __forceinline__ float sigm(float x)  { return 1.0f / (1.0f + expf(-x)); }
static __device__ __forceinline__ float splus(float x) { return fmaxf(x, 0.0f) + log1pf(expf(-fabsf(x))); }

static __device__ __forceinline__ float block_sum(float v, float* red) {
    int warp = threadIdx.x >> 5, lane = threadIdx.x & 31;
    v = warp_sum(v);
    if (!lane) red[warp] = v;
    __syncthreads();
    if (warp == 0) { float q = red[lane]; q = warp_sum(q); if (!lane) red[0] = q; }
    __syncthreads();
    float r = red[0];
    __syncthreads();
    return r;
}

// Single-warp softmax over arr[0..511]; only the executing warp participates.
static __device__ __forceinline__ void warp_softmax512(float* arr) {
    int lane = threadIdx.x & 31;
    float v[16];
    float mx = -3.402823466e38f;
#pragma unroll
    for (int k = 0; k < 16; k++) { v[k] = arr[lane + 32 * k]; mx = fmaxf(mx, v[k]); }
#pragma unroll
    for (int o = 16; o; o >>= 1) mx = fmaxf(mx, __shfl_xor_sync(0xffffffffu, mx, o));
    float s = 0.0f;
#pragma unroll
    for (int k = 0; k < 16; k++) { v[k] = expf(v[k] - mx); s += v[k]; }
#pragma unroll
    for (int o = 16; o; o >>= 1) s += __shfl_xor_sync(0xffffffffu, s, o);
    float inv = 1.0f / s;
#pragma unroll
    for (int k = 0; k < 16; k++) arr[lane + 32 * k] = v[k] * inv;
}

#define BARA() asm volatile("bar.sync 1, 512;" ::: "memory")   // warps 0-15
#define BARB() asm volatile("bar.sync 2, 512;" ::: "memory")   // warps 16-31
#define BARC() asm volatile("bar.sync 3, 256;" ::: "memory")   // warps 24-31

extern __shared__ float S[];

__global__ __launch_bounds__(NT, 1)
void dnc_kernel(const float* __restrict__ x,
                const float* __restrict__ W_ih, const float* __restrict__ b_ih,
                const float* __restrict__ W_hh, const float* __restrict__ b_hh,
                const float* __restrict__ W_out, const float* __restrict__ b_out,
                const float* __restrict__ W_int, const float* __restrict__ b_int,
                const float* __restrict__ W_mem, const float* __restrict__ b_mem,
                float* __restrict__ y_out)
{
    const int b    = blockIdx.x;
    const int tid  = threadIdx.x;
    const int warp = tid >> 5;
    const int lane = tid & 31;

    // ---- shared memory layout ----
    float* mem   = S;              // 32768  mem[512][64]
    float* h     = mem + 32768;    // 512
    float* c     = h + 512;        // 512
    float* inp   = c + 512;        // 512 : [unused(256), last_read(256)]
    float* gates = inp + 512;      // 2048 (alias: skey u64[512]; nww at +1024)
    float* outv  = gates + 2048;   // 512
    float* xi    = outv + 512;     // 480
    float* usage = xi + 480;       // 512
    float* wcw   = usage + 512;    // 512
    float* alloc = wcw + 512;      // 512
    float* wwv   = alloc + 512;    // 512
    float* prec  = wwv + 512;      // 512
    float* rw    = prec + 512;     // 2048 : read_w[4][512]
    float* fwd   = rw + 2048;      // 2048 (alias at init: xall staging, spans 8576 floats)
    float* bwd   = fwd + 2048;     // 2048
    float* rwp01 = bwd + 2048;     // 1024 : float2[512] (rw0,rw1)
    float* rwp23 = rwp01 + 1024;   // 1024 : float2[512] (rw2,rw3)
    float* cw    = rwp23 + 1024;   // 2048
    float* rk    = cw + 2048;      // 256
    float* wkey  = rk + 256;       // 64
    float* ers   = wkey + 64;      // 64
    float* wv    = ers + 64;       // 64
    float* sc    = wv + 64;        // 32
    float* red   = sc + 32;        // 32
    // total 50656 floats = 202624 bytes
    ull*   skey = (ull*)gates;
    float* nww  = gates + 1024;

    float* Lb   = g_link + (size_t)b * MDIM * MDIM;
    float* preb = g_pre + (size_t)b * 2048 * TT;

    // ---- init state ----
    for (int i = tid; i < MDIM * WDIM; i += NT) mem[i] = 0.0f;
    for (int i = tid; i < 512; i += NT) { h[i] = 0.f; c[i] = 0.f; usage[i] = 0.f; prec[i] = 0.f; wwv[i] = 0.f; }
    for (int i = tid; i < 2048; i += NT) rw[i] = 0.0f;
    if (tid < 256) inp[256 + tid] = 0.0f;
    {
        float4* L4 = (float4*)Lb;
        for (int i = tid; i < MDIM * MDIM / 4; i += NT) L4[i] = make_float4(0.f, 0.f, 0.f, 0.f);
    }
    // stage all x_t into smem scratch (fwd.. region; dead at init). Row stride 268 floats.
    {
        float* xall = fwd;
        for (int i = tid; i < TT * INDIM; i += NT) {
            int tt = i >> 8, e = i & 255;
            xall[tt * 268 + e] = x[((size_t)b * TT + tt) * INDIM + e];
        }
    }
    __syncthreads();
    // precompute g_pre[b][o][t] = W_ih[o,0:256] . x_t   (lane = t)
    {
        const float* xall = fwd;
        const ulonglong2* xs = (const ulonglong2*)(xall + lane * 268);
        for (int o = warp; o < 2048; o += NWARP) {
            const float4* wrow = (const float4*)(W_ih + (size_t)o * 512);
            ull acc = 0;
#pragma unroll 8
            for (int k = 0; k < 64; k++) {
                float4 w = wrow[k];          // uniform across lanes (broadcast)
                ulonglong2 xv = xs[k];
                acc = fma2(xv.x, pk2(w.x, w.y), acc);
                acc = fma2(xv.y, pk2(w.z, w.w), acc);
            }
            float2 f = upk2(acc);
            preb[(size_t)o * TT + lane] = f.x + f.y;
        }
    }
    __syncthreads();

    for (int t = 0; t < TT; t++) {
        // ---- 1. gates GEMV: pre[o][t] + W_ih[o,256:512].last_read + W_hh[o].h ----
        // Vector slices hoisted to registers once per warp (kills per-row LDS traffic).
        {
            const ulonglong2* vrp = (const ulonglong2*)(inp + 256);
            const ulonglong2* vhp = (const ulonglong2*)h;
            ulonglong2 vr0 = vrp[lane], vr1 = vrp[lane + 32];
            ulonglong2 vh0 = vhp[lane], vh1 = vhp[lane + 32];
            ulonglong2 vh2 = vhp[lane + 64], vh3 = vhp[lane + 96];
            for (int o = warp; o < 4 * HDIM; o += NWARP) {
                float pre = preb[(size_t)o * TT + t];
                const ulonglong2* wr = (const ulonglong2*)(W_ih + (size_t)o * 512 + 256);
                const ulonglong2* wh = (const ulonglong2*)(W_hh + (size_t)o * 512);
                ulonglong2 a0 = wr[lane], a1 = wr[lane + 32];
                ulonglong2 b0 = wh[lane], b1 = wh[lane + 32];
                ulonglong2 b2 = wh[lane + 64], b3 = wh[lane + 96];
                ull acc = 0;
                acc = fma2(a0.x, vr0.x, acc); acc = fma2(a0.y, vr0.y, acc);
                acc = fma2(a1.x, vr1.x, acc); acc = fma2(a1.y, vr1.y, acc);
                acc = fma2(b0.x, vh0.x, acc); acc = fma2(b0.y, vh0.y, acc);
                acc = fma2(b1.x, vh1.x, acc); acc = fma2(b1.y, vh1.y, acc);
                acc = fma2(b2.x, vh2.x, acc); acc = fma2(b2.y, vh2.y, acc);
                acc = fma2(b3.x, vh3.x, acc); acc = fma2(b3.y, vh3.y, acc);
                float2 f = upk2(acc);
                float s = warp_sum(f.x + f.y);
                if (!lane) gates[o] = s + pre + b_ih[o] + b_hh[o];
            }
        }
        __syncthreads();

        // ---- 2. LSTM cell ----
        if (tid < HDIM) {
            float gi = sigm(gates[tid]);
            float gf = sigm(gates[HDIM + tid]);
            float gg = tanhf(gates[2 * HDIM + tid]);
            float go = sigm(gates[3 * HDIM + tid]);
            float cn = gf * c[tid] + gi * gg;
            c[tid] = cn;
            h[tid] = go * tanhf(cn);
        }
        __syncthreads();

        // ---- 3. out/xi GEMV (h slice hoisted) ----
        {
            const ulonglong2* vhp = (const ulonglong2*)h;
            ulonglong2 v0 = vhp[lane], v1 = vhp[lane + 32];
            ulonglong2 v2 = vhp[lane + 64], v3 = vhp[lane + 96];
            for (int o = warp; o < 983; o += NWARP) {
                const float* wr = (o < 512) ? (W_out + (size_t)o * 512)
                                            : (W_int + (size_t)(o - 512) * 512);
                const ulonglong2* w2 = (const ulonglong2*)wr;
                ulonglong2 a0 = w2[lane], a1 = w2[lane + 32];
                ulonglong2 a2 = w2[lane + 64], a3 = w2[lane + 96];
                ull acc = 0;
                acc = fma2(a0.x, v0.x, acc); acc = fma2(a0.y, v0.y, acc);
                acc = fma2(a1.x, v1.x, acc); acc = fma2(a1.y, v1.y, acc);
                acc = fma2(a2.x, v2.x, acc); acc = fma2(a2.y, v2.y, acc);
                acc = fma2(a3.x, v3.x, acc); acc = fma2(a3.y, v3.y, acc);
                float2 f = upk2(acc);
                float s = warp_sum(f.x + f.y);
                if (!lane) {
                    if (o < 512) outv[o] = s + b_out[o];
                    else         xi[o - 512] = s + b_int[o - 512];
                }
            }
        }
        __syncthreads();

        // ---- 4. parse interface ----
        if (tid < 256)       rk[tid]         = tanhf(xi[tid]);
        else if (tid < 320)  wkey[tid - 256] = tanhf(xi[260 + (tid - 256)]);
        else if (tid < 384)  ers[tid - 320]  = sigm(xi[325 + (tid - 320)]);
        else if (tid < 448)  wv[tid - 384]   = tanhf(xi[389 + (tid - 384)]);
        else if (tid < 452)  sc[5 + (tid - 448)]  = splus(xi[256 + (tid - 448)]);
        else if (tid == 452) sc[9]  = splus(xi[324]);
        else if (tid < 457)  sc[10 + (tid - 453)] = sigm(xi[453 + (tid - 453)]);
        else if (tid == 457) sc[14] = sigm(xi[457]);
        else if (tid == 458) sc[15] = sigm(xi[458]);
        else if (tid < 463) {
            int r = tid - 459;
            float a = xi[459 + 3 * r], bm = xi[460 + 3 * r], cm = xi[461 + 3 * r];
            float mx = fmaxf(a, fmaxf(bm, cm));
            float ea = expf(a - mx), eb = expf(bm - mx), ec = expf(cm - mx);
            float s = ea + eb + ec;
            sc[16 + 3 * r] = ea / s; sc[17 + 3 * r] = eb / s; sc[18 + 3 * r] = ec / s;
        }
        __syncthreads();

        // ---- 5. key norms + usage update ----
        if (warp < 5) {
            const float* kp = (warp == 0) ? wkey : (rk + (warp - 1) * 64);
            float a = kp[lane], bq = kp[lane + 32];
            float ss = warp_sum(a * a + bq * bq);
            if (!lane) sc[warp] = 1.0f / (sqrtf(ss) + DELTAF);
        }
        if (tid < MDIM) {
            float u = usage[tid];
            u = u + (1.0f - u) * wwv[tid];          // old write_w
            float psi = 1.0f;
#pragma unroll
            for (int r = 0; r < RHEADS; r++) psi *= (1.0f - sc[10 + r] * rw[r * MDIM + tid]);
            usage[tid] = u * psi;
        }
        __syncthreads();

        // ==== SPLIT 1: [warps 0-15] wcw dots+softmax  ||  [16-31] sort+alloc ====
        if (tid < 512) {
            float ikn = sc[0], wstr = sc[9];
            for (int m = warp; m < MDIM; m += 16) {
                float a = mem[m * 64 + lane], bq = mem[m * 64 + lane + 32];
                float ss = a * a + bq * bq;
                float dk = a * wkey[lane] + bq * wkey[lane + 32];
#pragma unroll
                for (int o = 16; o; o >>= 1) {
                    ss += __shfl_down_sync(0xffffffffu, ss, o);
                    dk += __shfl_down_sync(0xffffffffu, dk, o);
                }
                if (!lane) {
                    float im = 1.0f / (sqrtf(ss) + DELTAF);
                    wcw[m] = dk * im * ikn * wstr;
                }
            }
            BARA();
            if (warp == 0) warp_softmax512(wcw);
        } else {
            // stable bitonic over (u, idx) in registers; shfl for j<32
            int p = tid - 512;
            int lane2 = p & 31;
            float u0 = DELTAF + (1.0f - DELTAF) * usage[p];
            ull key = ((ull)__float_as_uint(u0) << 32) | (unsigned)p;
            for (int k = 2; k <= MDIM; k <<= 1) {
                for (int j = k >> 1; j; j >>= 1) {
                    bool up    = ((p & k) == 0);
                    bool lower = ((p & j) == 0);
                    ull v;
                    if (j < 32) {
                        v = __shfl_xor_sync(0xffffffffu, key, j);
                    } else {
                        skey[p] = key;
                        BARB();
                        v = skey[p ^ j];
                        BARB();
                    }
                    bool keepmin = (lower == up);
                    bool take = keepmin ? (v < key) : (v > key);
                    key = take ? v : key;
                }
            }
            // exclusive cumprod of sorted u via warp-shuffle scan
            float su = __uint_as_float((unsigned)(key >> 32));
            float* us = (float*)skey;       // safe: sort's smem phase fully drained
            us[p] = su;
            BARB();
            float v = (p == 0) ? 1.0f : us[p - 1];
#pragma unroll
            for (int o = 1; o < 32; o <<= 1) {
                float tpr = __shfl_up_sync(0xffffffffu, v, o);
                if (lane2 >= o) v *= tpr;
            }
            int wg = p >> 5;
            if (lane2 == 31) red[16 + wg] = v;
            BARB();
            float pre = 1.0f;
            for (int w = 0; w < wg; w++) pre *= red[16 + w];
            unsigned idx = (unsigned)(key & 0xffffffffu);
            alloc[idx] = (1.0f - su) * (pre * v);
        }
        __syncthreads();

        // ---- 6. new write weights (+negated) ----
        if (tid < MDIM) {
            float ag = sc[14], wg = sc[15];
            float w_ = wg * (ag * alloc[tid] + (1.0f - ag) * wcw[tid]);
            wwv[tid] = w_;
            nww[tid] = -w_;
        }
        float sumww = block_sum((tid < MDIM) ? wwv[tid] : 0.0f, red);

        // ==== SPLIT 2: [warps 0-23] link A  ||  [24-31] mem update + cw dots ====
        if (tid < 768) {
            // link pass A: L update + fwd (OLD prec, OLD rw); diagonal post-fix
            const ulonglong2* nw2 = (const ulonglong2*)nww;
            const ulonglong2* pr2 = (const ulonglong2*)prec;
            const ulonglong2* r0b = (const ulonglong2*)(rw);
            const ulonglong2* r1b = (const ulonglong2*)(rw + MDIM);
            const ulonglong2* r2b = (const ulonglong2*)(rw + 2 * MDIM);
            const ulonglong2* r3b = (const ulonglong2*)(rw + 3 * MDIM);
            for (int i = warp; i < MDIM; i += 24) {
                float wwi = wwv[i];
                ull wwi2 = pk2(wwi, wwi);
                ull omw2 = pk2(1.0f - wwi, 1.0f - wwi);
                ull f0 = 0, f1 = 0, f2 = 0, f3 = 0;
                ulonglong2* row = (ulonglong2*)(Lb + (size_t)i * MDIM);
#pragma unroll
                for (int kk = 0; kk < 4; kk++) {
                    int k = lane + (kk << 5);
                    ulonglong2 l  = row[k];
                    ulonglong2 nj = nw2[k], pj = pr2[k];
                    ull c0 = add2(omw2, nj.x);
                    ull c1 = add2(omw2, nj.y);
                    ull n0 = fma2(wwi2, pj.x, mul2(c0, l.x));
                    ull n1 = fma2(wwi2, pj.y, mul2(c1, l.y));
                    ulonglong2 nout; nout.x = n0; nout.y = n1;
                    row[k] = nout;
                    ulonglong2 r0 = r0b[k]; f0 = fma2(n0, r0.x, f0); f0 = fma2(n1, r0.y, f0);
                    ulonglong2 r1 = r1b[k]; f1 = fma2(n0, r1.x, f1); f1 = fma2(n1, r1.y, f1);
                    ulonglong2 r2 = r2b[k]; f2 = fma2(n0, r2.x, f2); f2 = fma2(n1, r2.y, f2);
                    ulonglong2 r3 = r3b[k]; f3 = fma2(n0, r3.x, f3); f3 = fma2(n1, r3.y, f3);
                }
                float2 a0 = upk2(f0), a1 = upk2(f1), a2 = upk2(f2), a3 = upk2(f3);
                float s0 = warp_sum(a0.x + a0.y);
                float s1 = warp_sum(a1.x + a1.y);
                float s2 = warp_sum(a2.x + a2.y);
                float s3 = warp_sum(a3.x + a3.y);
                if (!lane) {
                    float corr = wwi * prec[i];   // OLD prec
                    fwd[i]            = s0 - corr * rw[i];
                    fwd[MDIM + i]     = s1 - corr * rw[MDIM + i];
                    fwd[2 * MDIM + i] = s2 - corr * rw[2 * MDIM + i];
                    fwd[3 * MDIM + i] = s3 - corr * rw[3 * MDIM + i];
                    Lb[(size_t)i * MDIM + i] = 0.0f;
                }
            }
        } else {
            int p3 = tid - 768;   // 0..255
            // zero bwd + stage OLD-rw head pairs for link B
            for (int q = p3; q < 2048; q += 256) bwd[q] = 0.0f;
            for (int q = p3; q < 512; q += 256) {
                ((float2*)rwp01)[q] = make_float2(rw[q], rw[MDIM + q]);
                ((float2*)rwp23)[q] = make_float2(rw[2 * MDIM + q], rw[3 * MDIM + q]);
            }
            // memory update
            for (int i = p3; i < MDIM * WDIM; i += 256) {
                int m = i >> 6, w_ = i & 63;
                float wwm = wwv[m];
                mem[i] = mem[i] * (1.0f - wwm * ers[w_]) + wwm * wv[w_];
            }
            BARC();
            // read content dots (NEW mem)
            for (int m = warp - 24; m < MDIM; m += 8) {
                float a = mem[m * 64 + lane], bq = mem[m * 64 + lane + 32];
                float ss = a * a + bq * bq;
                float d0 = a * rk[lane]       + bq * rk[lane + 32];
                float d1 = a * rk[64 + lane]  + bq * rk[96 + lane];
                float d2 = a * rk[128 + lane] + bq * rk[160 + lane];
                float d3 = a * rk[192 + lane] + bq * rk[224 + lane];
#pragma unroll
                for (int o = 16; o; o >>= 1) {
                    ss += __shfl_down_sync(0xffffffffu, ss, o);
                    d0 += __shfl_down_sync(0xffffffffu, d0, o);
                    d1 += __shfl_down_sync(0xffffffffu, d1, o);
                    d2 += __shfl_down_sync(0xffffffffu, d2, o);
                    d3 += __shfl_down_sync(0xffffffffu, d3, o);
                }
                if (!lane) {
                    float im = 1.0f / (sqrtf(ss) + DELTAF);
                    cw[m]            = d0 * im * sc[1] * sc[5];
                    cw[MDIM + m]     = d1 * im * sc[2] * sc[6];
                    cw[2 * MDIM + m] = d2 * im * sc[3] * sc[7];
                    cw[3 * MDIM + m] = d3 * im * sc[4] * sc[8];
                }
            }
        }
        __syncthreads();

        // ---- 7. precedence update (link A consumed OLD prec) ----
        if (tid < MDIM) prec[tid] = (1.0f - sumww) * prec[tid] + wwv[tid];

        // ---- 8. link pass B: bwd[h][j] = sum_i rw_h[i] * L_new[i][j] ----
        {
            int ig = warp >> 2, jb = warp & 3;
            const float* Lbase = Lb + (size_t)(ig * 64) * MDIM + jb * 128 + lane * 4;
            const ull* rp01 = (const ull*)rwp01 + ig * 64;
            const ull* rp23 = (const ull*)rwp23 + ig * 64;
            ull b01[4] = {0, 0, 0, 0}, b23[4] = {0, 0, 0, 0};
#pragma unroll 4
            for (int ii = 0; ii < 64; ii++) {
                float4 l = *(const float4*)(Lbase + (size_t)ii * MDIM);
                ull r01 = rp01[ii], r23 = rp23[ii];
                ull l0 = pk2(l.x, l.x), l1 = pk2(l.y, l.y);
                ull l2 = pk2(l.z, l.z), l3 = pk2(l.w, l.w);
                b01[0] = fma2(l0, r01, b01[0]); b01[1] = fma2(l1, r01, b01[1]);
                b01[2] = fma2(l2, r01, b01[2]); b01[3] = fma2(l3, r01, b01[3]);
                b23[0] = fma2(l0, r23, b23[0]); b23[1] = fma2(l1, r23, b23[1]);
                b23[2] = fma2(l2, r23, b23[2]); b23[3] = fma2(l3, r23, b23[3]);
            }
            int jbase = jb * 128 + lane * 4;
#pragma unroll
            for (int e = 0; e < 4; e++) {
                float2 v01 = upk2(b01[e]), v23 = upk2(b23[e]);
                atomicAdd(&bwd[jbase + e],            v01.x);
                atomicAdd(&bwd[MDIM + jbase + e],     v01.y);
                atomicAdd(&bwd[2 * MDIM + jbase + e], v23.x);
                atomicAdd(&bwd[3 * MDIM + jbase + e], v23.y);
            }
        }
        __syncthreads();

        // ---- 9. softmax read-content weights ----
        if (warp < 4) warp_softmax512(cw + warp * MDIM);
        __syncthreads();

        // ---- 10. new read weights ----
        for (int q = tid; q < RHEADS * MDIM; q += NT) {
            int r = q >> 9;
            rw[q] = sc[16 + 3 * r] * bwd[q] + sc[17 + 3 * r] * fwd[q] + sc[18 + 3 * r] * cw[q];
        }
        __syncthreads();

        // ---- 11. read vectors -> last_read ----
        {
            int pair = tid >> 2, q4 = tid & 3;
            int r = pair >> 6, w_ = pair & 63;
            const float* rwr = rw + r * MDIM;
            float acc = 0.0f;
            int m0 = q4 << 7;
#pragma unroll 8
            for (int mm = m0; mm < m0 + 128; mm++) acc += rwr[mm] * mem[mm * 64 + w_];
#pragma unroll
            for (int o = 2; o; o >>= 1) acc += __shfl_down_sync(0xffffffffu, acc, o, 4);
            if (q4 == 0) inp[256 + pair] = acc;
        }
        __syncthreads();

        // ---- 12. output GEMV (vector slices hoisted) ----
        {
            float* yrow = y_out + ((size_t)b * TT + t) * INDIM;
            const ulonglong2* v1 = (const ulonglong2*)outv;        // 128 ull2
            const ulonglong2* v2 = (const ulonglong2*)(inp + 256); // 64 ull2
            ulonglong2 y0 = v1[lane], y1 = v1[lane + 32];
            ulonglong2 y2 = v1[lane + 64], y3 = v1[lane + 96];
            ulonglong2 y4 = v2[lane], y5 = v2[lane + 32];
            for (int o = warp; o < INDIM; o += NWARP) {
                const ulonglong2* w2 = (const ulonglong2*)(W_mem + (size_t)o * 768);
                ulonglong2 a0 = w2[lane], a1 = w2[lane + 32];
                ulonglong2 a2 = w2[lane + 64], a3 = w2[lane + 96];
                ulonglong2 a4 = w2[lane + 128], a5 = w2[lane + 160];
                ull acc = 0;
                acc = fma2(a0.x, y0.x, acc); acc = fma2(a0.y, y0.y, acc);
                acc = fma2(a1.x, y1.x, acc); acc = fma2(a1.y, y1.y, acc);
                acc = fma2(a2.x, y2.x, acc); acc = fma2(a2.y, y2.y, acc);
                acc = fma2(a3.x, y3.x, acc); acc = fma2(a3.y, y3.y, acc);
                acc = fma2(a4.x, y4.x, acc); acc = fma2(a4.y, y4.y, acc);
                acc = fma2(a5.x, y5.x, acc); acc = fma2(a5.y, y5.y, acc);
                float2 f = upk2(acc);
                float s = warp_sum(f.x + f.y);
                if (!lane) yrow[o] = s + b_mem[o];
            }
        }
        __syncthreads();
    }
}

extern "C" void kernel_launch(void* const* d_in, const int* in_sizes, int n_in,
                              void* d_out, int out_size) {
    (void)in_sizes; (void)n_in; (void)out_size;
    const int SMEM_BYTES = 50656 * 4;  // 202624
    cudaFuncSetAttribute(dnc_kernel, cudaFuncAttributeMaxDynamicSharedMemorySize, SMEM_BYTES);
    dnc_kernel<<<BB, NT, SMEM_BYTES>>>(
        (const float*)d_in[0],
        (const float*)d_in[1], (const float*)d_in[2],
        (const float*)d_in[3], (const float*)d_in[4],
        (const float*)d_in[5], (const float*)d_in[6],
        (const float*)d_in[7], (const float*)d_in[8],
        (const float*)d_in[9], (const float*)d_in[10],
        (float*)d_out);
}

// round 14
// speedup vs baseline: 2.1238x; 1.9379x over previous
#include <cuda_runtime.h>
#include <math.h>
#include <stdint.h>

#define BB     16
#define TT     32
#define INDIM  256
#define HDIM   512
#define RHEADS 4
#define WDIM   64
#define MDIM   512
#define DELTAF 1e-6f

typedef unsigned long long ull;

// ---------------- global state ----------------
__device__ float g_link[(size_t)BB * MDIM * MDIM];   // 16 MB
__device__ float g_mem [BB][MDIM * WDIM];            // 2 MB
__device__ float g_h   [BB][HDIM];
__device__ float g_c   [BB][HDIM];
__device__ float g_lastread[BB][256];
__device__ float g_prec[2][BB][MDIM];                // ping-pong
__device__ float g_rw  [2][BB][4 * MDIM];            // ping-pong
__device__ float g_usage[BB][MDIM];
__device__ float g_wwv [BB][MDIM];
__device__ float g_outv[BB][512];
__device__ float g_xi  [BB][480];
__device__ float g_fwd [BB][4 * MDIM];
__device__ float g_cw  [BB][4 * MDIM];
__device__ float g_bwdp[BB][4][4 * MDIM];
__device__ float g_modes[BB][12];
__device__ float g_sumww[BB];

// ---------------- helpers ----------------
static __device__ __forceinline__ ull pk2(float a, float b) {
    ull r; asm("mov.b64 %0,{%1,%2};" : "=l"(r) : "f"(a), "f"(b)); return r;
}
static __device__ __forceinline__ float2 upk2(ull v) {
    float2 f; asm("mov.b64 {%0,%1},%2;" : "=f"(f.x), "=f"(f.y) : "l"(v)); return f;
}
static __device__ __forceinline__ ull add2(ull a, ull b) {
    ull d; asm("add.rn.f32x2 %0,%1,%2;" : "=l"(d) : "l"(a), "l"(b)); return d;
}
static __device__ __forceinline__ ull mul2(ull a, ull b) {
    ull d; asm("mul.rn.f32x2 %0,%1,%2;" : "=l"(d) : "l"(a), "l"(b)); return d;
}
static __device__ __forceinline__ ull fma2(ull a, ull b, ull c) {
    ull d; asm("fma.rn.f32x2 %0,%1,%2,%3;" : "=l"(d) : "l"(a), "l"(b), "l"(c)); return d;
}
static __device__ __forceinline__ float warp_sum(float v) {
#pragma unroll
    for (int o = 16; o; o >>= 1) v += __shfl_down_sync(0xffffffffu, v, o);
    return v;
}
static __device__ __forceinline__ float sigm(float x)  { return 1.0f / (1.0f + expf(-x)); }
static __device__ __forceinline__ float splus(float x) { return fmaxf(x, 0.0f) + log1pf(expf(-fabsf(x))); }

static __device__ __forceinline__ float block_sum(float v, float* red) {
    int warp = threadIdx.x >> 5, lane = threadIdx.x & 31;
    v = warp_sum(v);
    if (!lane) red[warp] = v;
    __syncthreads();
    if (warp == 0) { float q = red[lane]; q = warp_sum(q); if (!lane) red[0] = q; }
    __syncthreads();
    float r = red[0];
    __syncthreads();
    return r;
}
static __device__ __forceinline__ void warp_softmax512(float* arr) {
    int lane = threadIdx.x & 31;
    float v[16];
    float mx = -3.402823466e38f;
#pragma unroll
    for (int k = 0; k < 16; k++) { v[k] = arr[lane + 32 * k]; mx = fmaxf(mx, v[k]); }
#pragma unroll
    for (int o = 16; o; o >>= 1) mx = fmaxf(mx, __shfl_xor_sync(0xffffffffu, mx, o));
    float s = 0.0f;
#pragma unroll
    for (int k = 0; k < 16; k++) { v[k] = expf(v[k] - mx); s += v[k]; }
#pragma unroll
    for (int o = 16; o; o >>= 1) s += __shfl_xor_sync(0xffffffffu, s, o);
    float inv = 1.0f / s;
#pragma unroll
    for (int k = 0; k < 16; k++) arr[lane + 32 * k] = v[k] * inv;
}

#define BARA() asm volatile("bar.sync 1, 512;" ::: "memory")   // warps 0-15
#define BARB() asm volatile("bar.sync 2, 512;" ::: "memory")   // warps 16-31

// ================= K0: init =================
__global__ void k_init() {
    size_t tid = blockIdx.x * (size_t)blockDim.x + threadIdx.x;
    size_t nt = (size_t)gridDim.x * blockDim.x;
    for (size_t i = tid; i < (size_t)BB * MDIM * MDIM; i += nt) g_link[i] = 0.0f;
    for (size_t i = tid; i < (size_t)BB * MDIM * WDIM; i += nt) ((float*)g_mem)[i] = 0.0f;
    for (size_t i = tid; i < (size_t)BB * HDIM; i += nt) { ((float*)g_h)[i] = 0.f; ((float*)g_c)[i] = 0.f; }
    for (size_t i = tid; i < (size_t)BB * 256; i += nt) ((float*)g_lastread)[i] = 0.0f;
    for (size_t i = tid; i < (size_t)2 * BB * MDIM; i += nt) ((float*)g_prec)[i] = 0.0f;
    for (size_t i = tid; i < (size_t)2 * BB * 4 * MDIM; i += nt) ((float*)g_rw)[i] = 0.0f;
    for (size_t i = tid; i < (size_t)BB * MDIM; i += nt) { ((float*)g_usage)[i] = 0.f; ((float*)g_wwv)[i] = 0.f; }
}

// ================= K1: gates GEMM + LSTM =================
// grid 64, block 256 (8 warps); warp = one hidden unit (4 gate rows), all 16 batches.
extern __shared__ float SH[];
__global__ __launch_bounds__(256, 1)
void k_gates(const float* __restrict__ x,
             const float* __restrict__ W_ih, const float* __restrict__ b_ih,
             const float* __restrict__ W_hh, const float* __restrict__ b_hh, int t)
{
    float* V = SH;   // [16][1024] = 64 KB: [x(256)|lastread(256)|h(512)]
    int tid = threadIdx.x, warp = tid >> 5, lane = tid & 31;
    for (int i = tid; i < 16 * 1024; i += 256) {
        int b = i >> 10, e = i & 1023;
        float v;
        if (e < 256)      v = x[((size_t)b * TT + t) * INDIM + e];
        else if (e < 512) v = g_lastread[b][e - 256];
        else              v = g_h[b][e - 512];
        V[i] = v;
    }
    __syncthreads();

    int u = blockIdx.x * 8 + warp;   // hidden unit 0..511
    ull wih[4][8], whh[4][8];
#pragma unroll
    for (int g = 0; g < 4; g++) {
        int r = g * HDIM + u;
        const ull* pih = (const ull*)(W_ih + (size_t)r * 512);
        const ull* phh = (const ull*)(W_hh + (size_t)r * 512);
#pragma unroll
        for (int j = 0; j < 8; j++) { wih[g][j] = pih[lane + 32 * j]; whh[g][j] = phh[lane + 32 * j]; }
    }
    for (int b = 0; b < 16; b++) {
        const ull* vb = (const ull*)(V + b * 1024);
        ull a0 = 0, a1 = 0, a2 = 0, a3 = 0;
#pragma unroll
        for (int j = 0; j < 8; j++) {
            ull vi = vb[lane + 32 * j];
            ull vh = vb[256 + lane + 32 * j];
            a0 = fma2(wih[0][j], vi, a0); a0 = fma2(whh[0][j], vh, a0);
            a1 = fma2(wih[1][j], vi, a1); a1 = fma2(whh[1][j], vh, a1);
            a2 = fma2(wih[2][j], vi, a2); a2 = fma2(whh[2][j], vh, a2);
            a3 = fma2(wih[3][j], vi, a3); a3 = fma2(whh[3][j], vh, a3);
        }
        float2 f0 = upk2(a0), f1 = upk2(a1), f2 = upk2(a2), f3 = upk2(a3);
        float s0 = warp_sum(f0.x + f0.y);
        float s1 = warp_sum(f1.x + f1.y);
        float s2 = warp_sum(f2.x + f2.y);
        float s3 = warp_sum(f3.x + f3.y);
        if (!lane) {
            float gi = sigm(s0 + b_ih[u]            + b_hh[u]);
            float gf = sigm(s1 + b_ih[HDIM + u]     + b_hh[HDIM + u]);
            float gg = tanhf(s2 + b_ih[2 * HDIM + u] + b_hh[2 * HDIM + u]);
            float go = sigm(s3 + b_ih[3 * HDIM + u] + b_hh[3 * HDIM + u]);
            float cn = gf * g_c[b][u] + gi * gg;
            g_c[b][u] = cn;
            g_h[b][u] = go * tanhf(cn);
        }
    }
}

// ================= K2: out/xi GEMM =================
// grid 31, block 256; warp = 4 rows, all 16 batches. rows 0..982.
__global__ __launch_bounds__(256, 1)
void k_outxi(const float* __restrict__ W_out, const float* __restrict__ b_out,
             const float* __restrict__ W_int, const float* __restrict__ b_int)
{
    float* V = SH;   // [16][512] = 32 KB (h)
    int tid = threadIdx.x, warp = tid >> 5, lane = tid & 31;
    for (int i = tid; i < 16 * 512; i += 256) V[i] = g_h[i >> 9][i & 511];
    __syncthreads();

    int r0 = blockIdx.x * 32 + warp * 4;
    ull w[4][8];
    bool ok[4];
#pragma unroll
    for (int q = 0; q < 4; q++) {
        int r = r0 + q;
        ok[q] = (r < 983);
        const float* wr = ok[q] ? ((r < 512) ? (W_out + (size_t)r * 512)
                                             : (W_int + (size_t)(r - 512) * 512))
                                : W_out;
        const ull* p = (const ull*)wr;
#pragma unroll
        for (int j = 0; j < 8; j++) w[q][j] = p[lane + 32 * j];
    }
    for (int b = 0; b < 16; b++) {
        const ull* vb = (const ull*)(V + b * 512);
        ull a0 = 0, a1 = 0, a2 = 0, a3 = 0;
#pragma unroll
        for (int j = 0; j < 8; j++) {
            ull v = vb[lane + 32 * j];
            a0 = fma2(w[0][j], v, a0);
            a1 = fma2(w[1][j], v, a1);
            a2 = fma2(w[2][j], v, a2);
            a3 = fma2(w[3][j], v, a3);
        }
        float2 f0 = upk2(a0), f1 = upk2(a1), f2 = upk2(a2), f3 = upk2(a3);
        float s[4];
        s[0] = warp_sum(f0.x + f0.y);
        s[1] = warp_sum(f1.x + f1.y);
        s[2] = warp_sum(f2.x + f2.y);
        s[3] = warp_sum(f3.x + f3.y);
        if (!lane) {
#pragma unroll
            for (int q = 0; q < 4; q++) {
                int r = r0 + q;
                if (!ok[q]) continue;
                if (r < 512) g_outv[b][r] = s[q] + b_out[r];
                else         g_xi[b][r - 512] = s[q] + b_int[r - 512];
            }
        }
    }
}

// ================= K3: per-batch memory ops =================
// grid 16, block 1024. parse, usage, wcw dots+softmax || sort+alloc, write_w,
// mem update fused with cw dots.
__global__ __launch_bounds__(1024, 1)
void k_membatch(int t)
{
    __shared__ float xi[512], rk[256], wkey[64], ers[64], wv[64], sc[32], red[48];
    __shared__ float u_arr[512], wcw[512], alloc[512], wwv_s[512];
    __shared__ ull  skey[512];
    const int b = blockIdx.x;
    const int tid = threadIdx.x, warp = tid >> 5, lane = tid & 31;
    const int oldp = t & 1;
    const float* memb = g_mem[b];
    float* membw = g_mem[b];

    if (tid < 480) xi[tid] = g_xi[b][tid];
    __syncthreads();

    // parse
    if (tid < 256)       rk[tid]         = tanhf(xi[tid]);
    else if (tid < 320)  wkey[tid - 256] = tanhf(xi[260 + (tid - 256)]);
    else if (tid < 384)  ers[tid - 320]  = sigm(xi[325 + (tid - 320)]);
    else if (tid < 448)  wv[tid - 384]   = tanhf(xi[389 + (tid - 384)]);
    else if (tid < 452)  sc[5 + (tid - 448)]  = splus(xi[256 + (tid - 448)]);
    else if (tid == 452) sc[9]  = splus(xi[324]);
    else if (tid < 457)  sc[10 + (tid - 453)] = sigm(xi[453 + (tid - 453)]);
    else if (tid == 457) sc[14] = sigm(xi[457]);
    else if (tid == 458) sc[15] = sigm(xi[458]);
    else if (tid < 463) {
        int r = tid - 459;
        float a = xi[459 + 3 * r], bm = xi[460 + 3 * r], cm = xi[461 + 3 * r];
        float mx = fmaxf(a, fmaxf(bm, cm));
        float ea = expf(a - mx), eb = expf(bm - mx), ec = expf(cm - mx);
        float s = ea + eb + ec;
        sc[16 + 3 * r] = ea / s; sc[17 + 3 * r] = eb / s; sc[18 + 3 * r] = ec / s;
    }
    __syncthreads();

    // key norms + usage update
    if (warp < 5) {
        const float* kp = (warp == 0) ? wkey : (rk + (warp - 1) * 64);
        float a = kp[lane], bq = kp[lane + 32];
        float ss = warp_sum(a * a + bq * bq);
        if (!lane) sc[warp] = 1.0f / (sqrtf(ss) + DELTAF);
    }
    if (tid < MDIM) {
        float u = g_usage[b][tid];
        u = u + (1.0f - u) * g_wwv[b][tid];         // OLD write_w
        float psi = 1.0f;
#pragma unroll
        for (int r = 0; r < RHEADS; r++) psi *= (1.0f - sc[10 + r] * g_rw[oldp][b][r * MDIM + tid]);
        u *= psi;
        g_usage[b][tid] = u;
        u_arr[tid] = DELTAF + (1.0f - DELTAF) * u;
    }
    __syncthreads();

    // SPLIT: warps 0-15 wcw dots+softmax || warps 16-31 sort+alloc
    if (tid < 512) {
        float ikn = sc[0], wstr = sc[9];
        for (int m = warp; m < MDIM; m += 16) {
            float a = memb[m * 64 + lane], bq = memb[m * 64 + lane + 32];
            float ss = a * a + bq * bq;
            float dk = a * wkey[lane] + bq * wkey[lane + 32];
#pragma unroll
            for (int o = 16; o; o >>= 1) {
                ss += __shfl_down_sync(0xffffffffu, ss, o);
                dk += __shfl_down_sync(0xffffffffu, dk, o);
            }
            if (!lane) {
                float im = 1.0f / (sqrtf(ss) + DELTAF);
                wcw[m] = dk * im * ikn * wstr;
            }
        }
        BARA();
        if (warp == 0) warp_softmax512(wcw);
    } else {
        int p = tid - 512;
        int lane2 = p & 31;
        ull key = ((ull)__float_as_uint(u_arr[p]) << 32) | (unsigned)p;
        for (int k = 2; k <= MDIM; k <<= 1) {
            for (int j = k >> 1; j; j >>= 1) {
                bool up    = ((p & k) == 0);
                bool lower = ((p & j) == 0);
                ull v;
                if (j < 32) {
                    v = __shfl_xor_sync(0xffffffffu, key, j);
                } else {
                    skey[p] = key;
                    BARB();
                    v = skey[p ^ j];
                    BARB();
                }
                bool keepmin = (lower == up);
                bool take = keepmin ? (v < key) : (v > key);
                key = take ? v : key;
            }
        }
        float su = __uint_as_float((unsigned)(key >> 32));
        float* us = (float*)skey;
        us[p] = su;
        BARB();
        float v = (p == 0) ? 1.0f : us[p - 1];
#pragma unroll
        for (int o = 1; o < 32; o <<= 1) {
            float tpr = __shfl_up_sync(0xffffffffu, v, o);
            if (lane2 >= o) v *= tpr;
        }
        int wg = p >> 5;
        if (lane2 == 31) red[16 + wg] = v;
        BARB();
        float pre = 1.0f;
        for (int w = 0; w < wg; w++) pre *= red[16 + w];
        unsigned idx = (unsigned)(key & 0xffffffffu);
        alloc[idx] = (1.0f - su) * (pre * v);
    }
    __syncthreads();

    // write weights
    if (tid < MDIM) {
        float ag = sc[14], wg = sc[15];
        float w_ = wg * (ag * alloc[tid] + (1.0f - ag) * wcw[tid]);
        wwv_s[tid] = w_;
        g_wwv[b][tid] = w_;
    }
    float sumww = block_sum((tid < MDIM) ? wwv_s[tid] : 0.0f, red);
    if (tid == 0) g_sumww[b] = sumww;
    if (tid < 12) g_modes[b][tid] = sc[16 + tid];

    // mem update fused with read-content dots (NEW mem)
    for (int m = warp; m < MDIM; m += 32) {
        float wwm = wwv_s[m];
        float ao = memb[m * 64 + lane], bo = memb[m * 64 + lane + 32];
        float a  = ao * (1.0f - wwm * ers[lane])      + wwm * wv[lane];
        float bq = bo * (1.0f - wwm * ers[lane + 32]) + wwm * wv[lane + 32];
        membw[m * 64 + lane]      = a;
        membw[m * 64 + lane + 32] = bq;
        float ss = a * a + bq * bq;
        float d0 = a * rk[lane]       + bq * rk[lane + 32];
        float d1 = a * rk[64 + lane]  + bq * rk[96 + lane];
        float d2 = a * rk[128 + lane] + bq * rk[160 + lane];
        float d3 = a * rk[192 + lane] + bq * rk[224 + lane];
#pragma unroll
        for (int o = 16; o; o >>= 1) {
            ss += __shfl_down_sync(0xffffffffu, ss, o);
            d0 += __shfl_down_sync(0xffffffffu, d0, o);
            d1 += __shfl_down_sync(0xffffffffu, d1, o);
            d2 += __shfl_down_sync(0xffffffffu, d2, o);
            d3 += __shfl_down_sync(0xffffffffu, d3, o);
        }
        if (!lane) {
            float im = 1.0f / (sqrtf(ss) + DELTAF);
            g_cw[b][m]            = d0 * im * sc[1] * sc[5];
            g_cw[b][MDIM + m]     = d1 * im * sc[2] * sc[6];
            g_cw[b][2 * MDIM + m] = d2 * im * sc[3] * sc[7];
            g_cw[b][3 * MDIM + m] = d3 * im * sc[4] * sc[8];
        }
    }
}

// ================= K4: link A (update + fwd) + bwd partials =================
// grid 64 (b = blk>>2, sub = blk&3: rows sub*128..+128), block 512 (16 warps x 8 rows).
__global__ __launch_bounds__(512, 1)
void k_link(int t)
{
    __shared__ float wwv_s[512], nww_s[512], prec_s[512], rw_s[2048], bwd_s[2048];
    const int b = blockIdx.x >> 2, sub = blockIdx.x & 3;
    const int tid = threadIdx.x, warp = tid >> 5, lane = tid & 31;
    const int oldp = t & 1;

    for (int i = tid; i < 512; i += 512) {
        float w_ = g_wwv[b][i];
        wwv_s[i] = w_; nww_s[i] = -w_;
        prec_s[i] = g_prec[oldp][b][i];
    }
    for (int i = tid; i < 2048; i += 512) { rw_s[i] = g_rw[oldp][b][i]; bwd_s[i] = 0.0f; }
    __syncthreads();

    float* Lb = g_link + ((size_t)b * MDIM + sub * 128) * MDIM;
    const ulonglong2* nw2 = (const ulonglong2*)nww_s;
    const ulonglong2* pr2 = (const ulonglong2*)prec_s;
    const ulonglong2* r0b = (const ulonglong2*)rw_s;
    const ulonglong2* r1b = (const ulonglong2*)(rw_s + 512);
    const ulonglong2* r2b = (const ulonglong2*)(rw_s + 1024);
    const ulonglong2* r3b = (const ulonglong2*)(rw_s + 1536);

    ull acc01[16], acc23[16];
#pragma unroll
    for (int s = 0; s < 16; s++) { acc01[s] = 0; acc23[s] = 0; }

    for (int q = 0; q < 8; q++) {
        int il = warp * 8 + q;
        int i  = sub * 128 + il;
        float wwi = wwv_s[i];
        ull wwi2 = pk2(wwi, wwi);
        ull omw2 = pk2(1.0f - wwi, 1.0f - wwi);
        ull rw01 = pk2(rw_s[i], rw_s[512 + i]);
        ull rw23 = pk2(rw_s[1024 + i], rw_s[1536 + i]);
        ull f0 = 0, f1 = 0, f2 = 0, f3 = 0;
        ulonglong2* row = (ulonglong2*)(Lb + (size_t)il * MDIM);
#pragma unroll
        for (int kk = 0; kk < 4; kk++) {
            int k = lane + (kk << 5);
            ulonglong2 l  = row[k];
            ulonglong2 nj = nw2[k], pj = pr2[k];
            ull c0 = add2(omw2, nj.x);
            ull c1 = add2(omw2, nj.y);
            ull n0 = fma2(wwi2, pj.x, mul2(c0, l.x));
            ull n1 = fma2(wwi2, pj.y, mul2(c1, l.y));
            ulonglong2 nout; nout.x = n0; nout.y = n1;
            row[k] = nout;
            ulonglong2 r0 = r0b[k]; f0 = fma2(n0, r0.x, f0); f0 = fma2(n1, r0.y, f0);
            ulonglong2 r1 = r1b[k]; f1 = fma2(n0, r1.x, f1); f1 = fma2(n1, r1.y, f1);
            ulonglong2 r2 = r2b[k]; f2 = fma2(n0, r2.x, f2); f2 = fma2(n1, r2.y, f2);
            ulonglong2 r3 = r3b[k]; f3 = fma2(n0, r3.x, f3); f3 = fma2(n1, r3.y, f3);
            // bwd accumulation (j-ownership fixed per lane)
            float2 e0 = upk2(n0), e1 = upk2(n1);
            int s = kk * 4;
            acc01[s]     = fma2(pk2(e0.x, e0.x), rw01, acc01[s]);
            acc01[s + 1] = fma2(pk2(e0.y, e0.y), rw01, acc01[s + 1]);
            acc01[s + 2] = fma2(pk2(e1.x, e1.x), rw01, acc01[s + 2]);
            acc01[s + 3] = fma2(pk2(e1.y, e1.y), rw01, acc01[s + 3]);
            acc23[s]     = fma2(pk2(e0.x, e0.x), rw23, acc23[s]);
            acc23[s + 1] = fma2(pk2(e0.y, e0.y), rw23, acc23[s + 1]);
            acc23[s + 2] = fma2(pk2(e1.x, e1.x), rw23, acc23[s + 2]);
            acc23[s + 3] = fma2(pk2(e1.y, e1.y), rw23, acc23[s + 3]);
        }
        __syncwarp();
        float2 a0 = upk2(f0), a1 = upk2(f1), a2 = upk2(f2), a3 = upk2(f3);
        float s0 = warp_sum(a0.x + a0.y);
        float s1 = warp_sum(a1.x + a1.y);
        float s2 = warp_sum(a2.x + a2.y);
        float s3 = warp_sum(a3.x + a3.y);
        if (!lane) {
            float corr = wwi * prec_s[i];
            g_fwd[b][i]            = s0 - corr * rw_s[i];
            g_fwd[b][MDIM + i]     = s1 - corr * rw_s[512 + i];
            g_fwd[b][2 * MDIM + i] = s2 - corr * rw_s[1024 + i];
            g_fwd[b][3 * MDIM + i] = s3 - corr * rw_s[1536 + i];
            Lb[(size_t)il * MDIM + i] = 0.0f;   // zero diagonal
        }
    }
    // fold per-thread bwd partials into smem
#pragma unroll
    for (int s = 0; s < 16; s++) {
        int j = 4 * (lane + ((s >> 2) << 5)) + (s & 3);
        float2 v01 = upk2(acc01[s]), v23 = upk2(acc23[s]);
        atomicAdd(&bwd_s[j],        v01.x);
        atomicAdd(&bwd_s[512 + j],  v01.y);
        atomicAdd(&bwd_s[1024 + j], v23.x);
        atomicAdd(&bwd_s[1536 + j], v23.y);
    }
    __syncthreads();
    // remove spurious diagonal contribution to bwd at j == i (own rows only)
    if (tid < 128) {
        int i = sub * 128 + tid;
        float corr = wwv_s[i] * prec_s[i];
#pragma unroll
        for (int h = 0; h < 4; h++) bwd_s[h * 512 + i] -= corr * rw_s[h * 512 + i];
    }
    __syncthreads();
    for (int i = tid; i < 2048; i += 512) g_bwdp[b][sub][i] = bwd_s[i];
}

// ================= K5: rw update + read vectors + prec =================
// grid 16, block 1024.
__global__ __launch_bounds__(1024, 1)
void k_readw(int t)
{
    __shared__ float cw_s[2048], rw_s[2048], bwd_s[2048], m_s[12];
    const int b = blockIdx.x;
    const int tid = threadIdx.x, warp = tid >> 5;
    const int oldp = t & 1, newp = oldp ^ 1;

    for (int i = tid; i < 2048; i += 1024) {
        cw_s[i]  = g_cw[b][i];
        bwd_s[i] = g_bwdp[b][0][i] + g_bwdp[b][1][i] + g_bwdp[b][2][i] + g_bwdp[b][3][i];
    }
    if (tid < 12) m_s[tid] = g_modes[b][tid];
    __syncthreads();

    if (warp < 4) warp_softmax512(cw_s + warp * 512);
    __syncthreads();

    for (int q = tid; q < 2048; q += 1024) {
        int r = q >> 9;
        float v = m_s[3 * r] * bwd_s[q] + m_s[3 * r + 1] * g_fwd[b][q] + m_s[3 * r + 2] * cw_s[q];
        rw_s[q] = v;
        g_rw[newp][b][q] = v;
    }
    if (tid < MDIM) {
        float sw = g_sumww[b];
        g_prec[newp][b][tid] = (1.0f - sw) * g_prec[oldp][b][tid] + g_wwv[b][tid];
    }
    __syncthreads();

    // read vectors: 4 threads per (r, w) output
    {
        int pair = tid >> 2, q4 = tid & 3;
        int r = pair >> 6, w_ = pair & 63;
        const float* rwr = rw_s + r * MDIM;
        const float* memb = g_mem[b];
        float acc = 0.0f;
        int m0 = q4 << 7;
#pragma unroll 8
        for (int mm = m0; mm < m0 + 128; mm++) acc += rwr[mm] * memb[mm * 64 + w_];
#pragma unroll
        for (int o = 2; o; o >>= 1) acc += __shfl_down_sync(0xffffffffu, acc, o, 4);
        if (q4 == 0) g_lastread[b][pair] = acc;
    }
}

// ================= K6: output GEMM =================
// grid 8, block 256; warp = 4 rows, all 16 batches.
__global__ __launch_bounds__(256, 1)
void k_y(const float* __restrict__ W_mem, const float* __restrict__ b_mem,
         float* __restrict__ y_out, int t)
{
    float* V = SH;   // [16][768] = 48 KB : [outv(512)|lastread(256)]
    int tid = threadIdx.x, warp = tid >> 5, lane = tid & 31;
    for (int i = tid; i < 16 * 768; i += 256) {
        int b = i / 768, e = i - b * 768;
        V[i] = (e < 512) ? g_outv[b][e] : g_lastread[b][e - 512];
    }
    __syncthreads();

    int r0 = blockIdx.x * 32 + warp * 4;
    ull w[4][12];
#pragma unroll
    for (int q = 0; q < 4; q++) {
        const ull* p = (const ull*)(W_mem + (size_t)(r0 + q) * 768);
#pragma unroll
        for (int j = 0; j < 12; j++) w[q][j] = p[lane + 32 * j];
    }
    for (int b = 0; b < 16; b++) {
        const ull* vb = (const ull*)(V + b * 768);
        ull a0 = 0, a1 = 0, a2 = 0, a3 = 0;
#pragma unroll
        for (int j = 0; j < 12; j++) {
            ull v = vb[lane + 32 * j];
            a0 = fma2(w[0][j], v, a0);
            a1 = fma2(w[1][j], v, a1);
            a2 = fma2(w[2][j], v, a2);
            a3 = fma2(w[3][j], v, a3);
        }
        float2 f0 = upk2(a0), f1 = upk2(a1), f2 = upk2(a2), f3 = upk2(a3);
        float s[4];
        s[0] = warp_sum(f0.x + f0.y);
        s[1] = warp_sum(f1.x + f1.y);
        s[2] = warp_sum(f2.x + f2.y);
        s[3] = warp_sum(f3.x + f3.y);
        if (!lane) {
            float* yrow = y_out + ((size_t)b * TT + t) * INDIM;
#pragma unroll
            for (int q = 0; q < 4; q++) yrow[r0 + q] = s[q] + b_mem[r0 + q];
        }
    }
}

// ================= launch =================
extern "C" void kernel_launch(void* const* d_in, const int* in_sizes, int n_in,
                              void* d_out, int out_size) {
    (void)in_sizes; (void)n_in; (void)out_size;
    const float* x     = (const float*)d_in[0];
    const float* W_ih  = (const float*)d_in[1];
    const float* b_ih  = (const float*)d_in[2];
    const float* W_hh  = (const float*)d_in[3];
    const float* b_hh  = (const float*)d_in[4];
    const float* W_out = (const float*)d_in[5];
    const float* b_out = (const float*)d_in[6];
    const float* W_int = (const float*)d_in[7];
    const float* b_int = (const float*)d_in[8];
    const float* W_mem = (const float*)d_in[9];
    const float* b_mem = (const float*)d_in[10];
    float* y = (float*)d_out;

    cudaFuncSetAttribute(k_gates, cudaFuncAttributeMaxDynamicSharedMemorySize, 65536);
    cudaFuncSetAttribute(k_outxi, cudaFuncAttributeMaxDynamicSharedMemorySize, 32768);
    cudaFuncSetAttribute(k_y,     cudaFuncAttributeMaxDynamicSharedMemorySize, 49152);

    k_init<<<128, 1024>>>();
    for (int t = 0; t < TT; t++) {
        k_gates<<<64, 256, 65536>>>(x, W_ih, b_ih, W_hh, b_hh, t);
        k_outxi<<<31, 256, 32768>>>(W_out, b_out, W_int, b_int);
        k_membatch<<<16, 1024>>>(t);
        k_link<<<64, 512>>>(t);
        k_readw<<<16, 1024>>>(t);
        k_y<<<8, 256, 49152>>>(W_mem, b_mem, y, t);
    }
}